// round 1
// baseline (speedup 1.0000x reference)
#include <cuda_runtime.h>
#include <cstdint>

// Problem constants (from reference)
#define V_NUM 80000
#define P_NUM 20
#define C_OUT 64
#define NY 640
#define NX 640
#define B_NUM 4

__device__ __constant__ float kVX   = 100.0f / 640.0f;           // 0.15625
__device__ __constant__ float kXOFF = 100.0f / 640.0f * 0.5f - 50.0f;

static constexpr float BN_EPS = 0.001f;
static constexpr size_t PLANE  = (size_t)NY * NX;                 // 409600
static constexpr size_t CANVAS = (size_t)B_NUM * C_OUT * PLANE;   // 104857600

// One warp per voxel. lane handles channels {lane, lane+32}.
__global__ void __launch_bounds__(128)
pillar_scatter_kernel(const float* __restrict__ voxels,
                      const int*   __restrict__ num_points,
                      const int*   __restrict__ coors,
                      const float* __restrict__ W,
                      const float* __restrict__ gamma,
                      const float* __restrict__ beta,
                      const float* __restrict__ rmean,
                      const float* __restrict__ rvar,
                      float*       __restrict__ out)
{
    const int warp_in_blk = threadIdx.x >> 5;
    const int v = blockIdx.x * (blockDim.x >> 5) + warp_in_blk;
    if (v >= V_NUM) return;
    const int lane = threadIdx.x & 31;

    const float4* __restrict__ vox =
        reinterpret_cast<const float4*>(voxels) + (size_t)v * P_NUM;

    int npv = num_points[v];
    npv = npv < 0 ? 0 : (npv > P_NUM ? P_NUM : npv);

    // --- mean over valid points (warp reduction) ---
    float sx = 0.f, sy = 0.f, sz = 0.f;
    if (lane < npv) {
        float4 pt = vox[lane];
        sx = pt.x; sy = pt.y; sz = pt.z;
    }
    #pragma unroll
    for (int o = 16; o; o >>= 1) {
        sx += __shfl_xor_sync(0xffffffffu, sx, o);
        sy += __shfl_xor_sync(0xffffffffu, sy, o);
        sz += __shfl_xor_sync(0xffffffffu, sz, o);
    }
    const float inv_n = 1.0f / (float)(npv > 1 ? npv : 1);
    const float mx = sx * inv_n, my = sy * inv_n, mz = sz * inv_n;

    // --- pillar center ---
    const int b  = coors[v * 4 + 0];
    const int yy = coors[v * 4 + 2];
    const int xx = coors[v * 4 + 3];
    const float cx = (float)xx * kVX + kXOFF;   // VX==VY, XOFF==YOFF (NX==NY)
    const float cy = (float)yy * kVX + kXOFF;

    // --- per-lane channel params ---
    const int c0 = lane, c1 = lane + 32;
    float w0[9], w1[9];
    #pragma unroll
    for (int i = 0; i < 9; i++) {
        w0[i] = W[i * C_OUT + c0];
        w1[i] = W[i * C_OUT + c1];
    }
    const float s0 = rsqrtf(rvar[c0] + BN_EPS) * gamma[c0];
    const float s1 = rsqrtf(rvar[c1] + BN_EPS) * gamma[c1];
    const float b0 = beta[c0] - rmean[c0] * s0;
    const float b1 = beta[c1] - rmean[c1] * s1;

    // invalid (masked-to-zero) points contribute relu(b) to the max
    float m0 = (npv < P_NUM) ? fmaxf(b0, 0.0f) : -3.4e38f;
    float m1 = (npv < P_NUM) ? fmaxf(b1, 0.0f) : -3.4e38f;

    for (int p = 0; p < npv; p++) {
        const float4 pt = vox[p];
        const float f4 = pt.x - mx;
        const float f5 = pt.y - my;
        const float f6 = pt.z - mz;
        const float f7 = pt.x - cx;
        const float f8 = pt.y - cy;

        float h0 = pt.x * w0[0];
        float h1 = pt.x * w1[0];
        h0 = fmaf(pt.y, w0[1], h0);  h1 = fmaf(pt.y, w1[1], h1);
        h0 = fmaf(pt.z, w0[2], h0);  h1 = fmaf(pt.z, w1[2], h1);
        h0 = fmaf(pt.w, w0[3], h0);  h1 = fmaf(pt.w, w1[3], h1);
        h0 = fmaf(f4,   w0[4], h0);  h1 = fmaf(f4,   w1[4], h1);
        h0 = fmaf(f5,   w0[5], h0);  h1 = fmaf(f5,   w1[5], h1);
        h0 = fmaf(f6,   w0[6], h0);  h1 = fmaf(f6,   w1[6], h1);
        h0 = fmaf(f7,   w0[7], h0);  h1 = fmaf(f7,   w1[7], h1);
        h0 = fmaf(f8,   w0[8], h0);  h1 = fmaf(f8,   w1[8], h1);

        h0 = fmaxf(fmaf(h0, s0, b0), 0.0f);
        h1 = fmaxf(fmaf(h1, s1, b1), 0.0f);
        m0 = fmaxf(m0, h0);
        m1 = fmaxf(m1, h1);
    }

    // --- scatter (unique pixels, no atomics needed) ---
    const size_t pix  = (size_t)yy * NX + xx;
    const size_t base = (size_t)b * C_OUT * PLANE + pix;
    out[base + (size_t)c0 * PLANE] = m0;
    out[base + (size_t)c1 * PLANE] = m1;
    if (lane == 0)
        out[CANVAS + (size_t)b * PLANE + pix] = 1.0f;
}

extern "C" void kernel_launch(void* const* d_in, const int* in_sizes, int n_in,
                              void* d_out, int out_size)
{
    const float* voxels     = (const float*)d_in[0];
    const int*   num_points = (const int*)  d_in[1];
    const int*   coors      = (const int*)  d_in[2];
    const float* W          = (const float*)d_in[3];
    const float* gamma      = (const float*)d_in[4];
    const float* beta       = (const float*)d_in[5];
    const float* rmean      = (const float*)d_in[6];
    const float* rvar       = (const float*)d_in[7];
    float* out = (float*)d_out;

    // Zero the whole output (canvas + occ); scatter kernel then overwrites
    // the 80000 occupied pixels.
    cudaMemsetAsync(out, 0, (size_t)out_size * sizeof(float));

    const int warps_per_block = 4;           // 128 threads
    const int blocks = (V_NUM + warps_per_block - 1) / warps_per_block;
    pillar_scatter_kernel<<<blocks, 128>>>(voxels, num_points, coors, W,
                                           gamma, beta, rmean, rvar, out);
}

// round 2
// speedup vs baseline: 1.9514x; 1.9514x over previous
#include <cuda_runtime.h>
#include <cstdint>

#define V_NUM 80000
#define P_NUM 20
#define C_OUT 64
#define NY 640
#define NX 640
#define B_NUM 4

static constexpr float BN_EPS = 0.001f;
static constexpr size_t PLANE  = (size_t)NY * NX;                 // 409600
static constexpr size_t CANVAS = (size_t)B_NUM * C_OUT * PLANE;   // 104857600
static constexpr int    MAP_N  = B_NUM * NY * NX;                 // 1638400

__device__ __constant__ float kVX   = 100.0f / 640.0f;
__device__ __constant__ float kXOFF = 100.0f / 640.0f * 0.5f - 50.0f;

// Scratch (static device allocations — allowed)
__device__ float g_feats[(size_t)V_NUM * C_OUT];   // 20.5 MB
__device__ int   g_map[MAP_N];                     // 6.6 MB, pixel -> voxel id or -1

// ---------------------------------------------------------------------------
// Kernel 1: clear inverse map to -1 (int4 stores)
// ---------------------------------------------------------------------------
__global__ void __launch_bounds__(256)
clear_map_kernel()
{
    int i = blockIdx.x * blockDim.x + threadIdx.x;          // int4 index
    if (i < MAP_N / 4) {
        reinterpret_cast<int4*>(g_map)[i] = make_int4(-1, -1, -1, -1);
    }
}

// ---------------------------------------------------------------------------
// Kernel 2: per-voxel feature compute -> g_feats (coalesced), id -> g_map
// One warp per voxel; lane handles channels {lane, lane+32}.
// ---------------------------------------------------------------------------
__global__ void __launch_bounds__(128)
compute_feats_kernel(const float* __restrict__ voxels,
                     const int*   __restrict__ num_points,
                     const int*   __restrict__ coors,
                     const float* __restrict__ W,
                     const float* __restrict__ gamma,
                     const float* __restrict__ beta,
                     const float* __restrict__ rmean,
                     const float* __restrict__ rvar)
{
    const int warp_in_blk = threadIdx.x >> 5;
    const int v = blockIdx.x * (blockDim.x >> 5) + warp_in_blk;
    if (v >= V_NUM) return;
    const int lane = threadIdx.x & 31;

    const float4* __restrict__ vox =
        reinterpret_cast<const float4*>(voxels) + (size_t)v * P_NUM;

    int npv = num_points[v];
    npv = npv < 0 ? 0 : (npv > P_NUM ? P_NUM : npv);

    // mean over valid points via warp reduction
    float sx = 0.f, sy = 0.f, sz = 0.f;
    if (lane < npv) {
        float4 pt = vox[lane];
        sx = pt.x; sy = pt.y; sz = pt.z;
    }
    #pragma unroll
    for (int o = 16; o; o >>= 1) {
        sx += __shfl_xor_sync(0xffffffffu, sx, o);
        sy += __shfl_xor_sync(0xffffffffu, sy, o);
        sz += __shfl_xor_sync(0xffffffffu, sz, o);
    }
    const float inv_n = 1.0f / (float)(npv > 1 ? npv : 1);
    const float mx = sx * inv_n, my = sy * inv_n, mz = sz * inv_n;

    const int b  = coors[v * 4 + 0];
    const int yy = coors[v * 4 + 2];
    const int xx = coors[v * 4 + 3];
    const float cx = (float)xx * kVX + kXOFF;
    const float cy = (float)yy * kVX + kXOFF;

    const int c0 = lane, c1 = lane + 32;
    float w0[9], w1[9];
    #pragma unroll
    for (int i = 0; i < 9; i++) {
        w0[i] = W[i * C_OUT + c0];
        w1[i] = W[i * C_OUT + c1];
    }
    const float s0 = rsqrtf(rvar[c0] + BN_EPS) * gamma[c0];
    const float s1 = rsqrtf(rvar[c1] + BN_EPS) * gamma[c1];
    const float b0 = beta[c0] - rmean[c0] * s0;
    const float b1 = beta[c1] - rmean[c1] * s1;

    // masked (invalid) points contribute relu(bias) to the max
    float m0 = (npv < P_NUM) ? fmaxf(b0, 0.0f) : -3.4e38f;
    float m1 = (npv < P_NUM) ? fmaxf(b1, 0.0f) : -3.4e38f;

    for (int p = 0; p < npv; p++) {
        const float4 pt = vox[p];
        const float f4 = pt.x - mx;
        const float f5 = pt.y - my;
        const float f6 = pt.z - mz;
        const float f7 = pt.x - cx;
        const float f8 = pt.y - cy;

        float h0 = pt.x * w0[0];
        float h1 = pt.x * w1[0];
        h0 = fmaf(pt.y, w0[1], h0);  h1 = fmaf(pt.y, w1[1], h1);
        h0 = fmaf(pt.z, w0[2], h0);  h1 = fmaf(pt.z, w1[2], h1);
        h0 = fmaf(pt.w, w0[3], h0);  h1 = fmaf(pt.w, w1[3], h1);
        h0 = fmaf(f4,   w0[4], h0);  h1 = fmaf(f4,   w1[4], h1);
        h0 = fmaf(f5,   w0[5], h0);  h1 = fmaf(f5,   w1[5], h1);
        h0 = fmaf(f6,   w0[6], h0);  h1 = fmaf(f6,   w1[6], h1);
        h0 = fmaf(f7,   w0[7], h0);  h1 = fmaf(f7,   w1[7], h1);
        h0 = fmaf(f8,   w0[8], h0);  h1 = fmaf(f8,   w1[8], h1);

        h0 = fmaxf(fmaf(h0, s0, b0), 0.0f);
        h1 = fmaxf(fmaf(h1, s1, b1), 0.0f);
        m0 = fmaxf(m0, h0);
        m1 = fmaxf(m1, h1);
    }

    // coalesced 128B stores
    g_feats[(size_t)v * C_OUT + c0] = m0;
    g_feats[(size_t)v * C_OUT + c1] = m1;
    if (lane == 0)
        g_map[b * (NY * NX) + yy * NX + xx] = v;
}

// ---------------------------------------------------------------------------
// Kernel 3: render the full output with coalesced float4 stores.
// Block = 256 threads, owns a 128-pixel x-tile of one (b, y) row, all 64 ch.
// Thread layout: lane-of-8-rows: row r = t>>5 handles channels r, r+8, ..., r+56;
// xq = (t&31) handles x quad [4*xq, 4*xq+3].
// ---------------------------------------------------------------------------
__global__ void __launch_bounds__(256)
render_kernel(float* __restrict__ out)
{
    __shared__ int map_s[128];

    const int b  = blockIdx.z;
    const int y  = blockIdx.y;
    const int x0 = blockIdx.x * 128;
    const int t  = threadIdx.x;

    const int pix_base = b * (NY * NX) + y * NX + x0;
    if (t < 128)
        map_s[t] = g_map[pix_base + t];
    __syncthreads();

    const int xq  = (t & 31) * 4;           // x offset within tile (quad)
    const int row = t >> 5;                 // 0..7

    const int v0 = map_s[xq + 0];
    const int v1 = map_s[xq + 1];
    const int v2 = map_s[xq + 2];
    const int v3 = map_s[xq + 3];
    const bool any = (v0 | v1 | v2 | v3) >= 0 ||
                     v0 >= 0 || v1 >= 0 || v2 >= 0 || v3 >= 0;

    const size_t out_xbase = (size_t)y * NX + x0 + xq;

    #pragma unroll
    for (int k = 0; k < 8; k++) {
        const int c = row + k * 8;
        float4 val = make_float4(0.f, 0.f, 0.f, 0.f);
        if (any) {
            if (v0 >= 0) val.x = g_feats[(size_t)v0 * C_OUT + c];
            if (v1 >= 0) val.y = g_feats[(size_t)v1 * C_OUT + c];
            if (v2 >= 0) val.z = g_feats[(size_t)v2 * C_OUT + c];
            if (v3 >= 0) val.w = g_feats[(size_t)v3 * C_OUT + c];
        }
        float4* dst = reinterpret_cast<float4*>(
            out + ((size_t)(b * C_OUT + c)) * PLANE + out_xbase);
        *dst = val;
    }

    // occupancy plane: first 32 threads write the 128-pixel tile
    if (t < 32) {
        float4 occ = make_float4(v0 >= 0 ? 1.f : 0.f,
                                 v1 >= 0 ? 1.f : 0.f,
                                 v2 >= 0 ? 1.f : 0.f,
                                 v3 >= 0 ? 1.f : 0.f);
        float4* dst = reinterpret_cast<float4*>(
            out + CANVAS + (size_t)b * PLANE + out_xbase);
        *dst = occ;
    }
}

extern "C" void kernel_launch(void* const* d_in, const int* in_sizes, int n_in,
                              void* d_out, int out_size)
{
    const float* voxels     = (const float*)d_in[0];
    const int*   num_points = (const int*)  d_in[1];
    const int*   coors      = (const int*)  d_in[2];
    const float* W          = (const float*)d_in[3];
    const float* gamma      = (const float*)d_in[4];
    const float* beta       = (const float*)d_in[5];
    const float* rmean      = (const float*)d_in[6];
    const float* rvar       = (const float*)d_in[7];
    float* out = (float*)d_out;

    // 1) reset inverse map
    clear_map_kernel<<<(MAP_N / 4 + 255) / 256, 256>>>();

    // 2) per-voxel features -> scratch (coalesced), ids -> map
    compute_feats_kernel<<<(V_NUM + 3) / 4, 128>>>(voxels, num_points, coors,
                                                   W, gamma, beta, rmean, rvar);

    // 3) coalesced render of canvas + occ
    dim3 grid(NX / 128, NY, B_NUM);
    render_kernel<<<grid, 256>>>(out);
}

// round 3
// speedup vs baseline: 2.4491x; 1.2551x over previous
#include <cuda_runtime.h>
#include <cstdint>

#define V_NUM 80000
#define P_NUM 20
#define C_OUT 64
#define NY 640
#define NX 640
#define B_NUM 4

static constexpr float BN_EPS = 0.001f;
static constexpr size_t PLANE  = (size_t)NY * NX;                 // 409600
static constexpr size_t CANVAS = (size_t)B_NUM * C_OUT * PLANE;   // 104857600
static constexpr int    MAP_N  = B_NUM * NY * NX;                 // 1638400

__device__ __constant__ float kVX   = 100.0f / 640.0f;
__device__ __constant__ float kXOFF = 100.0f / 640.0f * 0.5f - 50.0f;

// Scratch. g_map / g_pix are zero-initialized at module load; the
// self-validation scheme below (g_pix[g_map[pix]] == pix) makes per-call
// clearing unnecessary: occupied pixels are rewritten every call, stale or
// initial-zero entries can never validate.
__device__ float g_feats[(size_t)V_NUM * C_OUT];   // 20.5 MB
__device__ int   g_map[MAP_N];                     // pixel -> voxel id
__device__ int   g_pix[V_NUM];                     // voxel id -> pixel

// ---------------------------------------------------------------------------
// Kernel 1: per-voxel features -> g_feats (coalesced), id <-> pixel links.
// One warp per voxel; lane handles channels {lane, lane+32}.
// Affine-folded GEMM: h = x*A + y*B + z*C + w*D + E_v   (BN scale pre-folded)
// ---------------------------------------------------------------------------
__global__ void __launch_bounds__(128)
compute_feats_kernel(const float* __restrict__ voxels,
                     const int*   __restrict__ num_points,
                     const int*   __restrict__ coors,
                     const float* __restrict__ W,
                     const float* __restrict__ gamma,
                     const float* __restrict__ beta,
                     const float* __restrict__ rmean,
                     const float* __restrict__ rvar)
{
    const int v = blockIdx.x * (blockDim.x >> 5) + (threadIdx.x >> 5);
    if (v >= V_NUM) return;
    const int lane = threadIdx.x & 31;

    const float4* __restrict__ vox =
        reinterpret_cast<const float4*>(voxels) + (size_t)v * P_NUM;

    int npv = num_points[v];
    npv = npv < 0 ? 0 : (npv > P_NUM ? P_NUM : npv);

    // mean over valid points via warp reduction
    float sx = 0.f, sy = 0.f, sz = 0.f;
    if (lane < npv) {
        float4 pt = vox[lane];
        sx = pt.x; sy = pt.y; sz = pt.z;
    }
    #pragma unroll
    for (int o = 16; o; o >>= 1) {
        sx += __shfl_xor_sync(0xffffffffu, sx, o);
        sy += __shfl_xor_sync(0xffffffffu, sy, o);
        sz += __shfl_xor_sync(0xffffffffu, sz, o);
    }
    const float inv_n = 1.0f / (float)(npv > 1 ? npv : 1);
    const float mx = sx * inv_n, my = sy * inv_n, mz = sz * inv_n;

    const int b  = coors[v * 4 + 0];
    const int yy = coors[v * 4 + 2];
    const int xx = coors[v * 4 + 3];
    const float cx = (float)xx * kVX + kXOFF;
    const float cy = (float)yy * kVX + kXOFF;

    const int c0 = lane, c1 = lane + 32;
    const float s0 = rsqrtf(rvar[c0] + BN_EPS) * gamma[c0];
    const float s1 = rsqrtf(rvar[c1] + BN_EPS) * gamma[c1];
    const float bb0 = beta[c0] - rmean[c0] * s0;   // BN bias (also masked-pt value)
    const float bb1 = beta[c1] - rmean[c1] * s1;

    // scaled weight rows
    float sw0[9], sw1[9];
    #pragma unroll
    for (int i = 0; i < 9; i++) {
        sw0[i] = W[i * C_OUT + c0] * s0;
        sw1[i] = W[i * C_OUT + c1] * s1;
    }
    const float A0 = sw0[0] + sw0[4] + sw0[7];
    const float B0 = sw0[1] + sw0[5] + sw0[8];
    const float C0 = sw0[2] + sw0[6];
    const float D0 = sw0[3];
    const float A1 = sw1[0] + sw1[4] + sw1[7];
    const float B1 = sw1[1] + sw1[5] + sw1[8];
    const float C1 = sw1[2] + sw1[6];
    const float D1 = sw1[3];
    // per-voxel constant term (mean + center contributions + BN bias)
    const float E0 = bb0 - (mx * sw0[4] + my * sw0[5] + mz * sw0[6]
                          + cx * sw0[7] + cy * sw0[8]);
    const float E1 = bb1 - (mx * sw1[4] + my * sw1[5] + mz * sw1[6]
                          + cx * sw1[7] + cy * sw1[8]);

    // masked (zero-feature) points contribute relu(BN bias) to the max
    float m0 = (npv < P_NUM) ? fmaxf(bb0, 0.0f) : -3.4e38f;
    float m1 = (npv < P_NUM) ? fmaxf(bb1, 0.0f) : -3.4e38f;

    for (int p = 0; p < npv; p++) {
        const float4 pt = vox[p];
        float h0 = fmaf(pt.x, A0, E0);
        float h1 = fmaf(pt.x, A1, E1);
        h0 = fmaf(pt.y, B0, h0);   h1 = fmaf(pt.y, B1, h1);
        h0 = fmaf(pt.z, C0, h0);   h1 = fmaf(pt.z, C1, h1);
        h0 = fmaf(pt.w, D0, h0);   h1 = fmaf(pt.w, D1, h1);
        m0 = fmaxf(m0, fmaxf(h0, 0.0f));
        m1 = fmaxf(m1, fmaxf(h1, 0.0f));
    }

    g_feats[(size_t)v * C_OUT + c0] = m0;
    g_feats[(size_t)v * C_OUT + c1] = m1;
    if (lane == 0) {
        const int pix = b * (NY * NX) + yy * NX + xx;
        g_map[pix] = v;
        g_pix[v]   = pix;
    }
}

// ---------------------------------------------------------------------------
// Kernel 2: coalesced render of canvas + occ.
// Block = 256 threads, owns 128 pixels of one (b,y) row, all 64 channels.
// ---------------------------------------------------------------------------
__global__ void __launch_bounds__(256)
render_kernel(float* __restrict__ out)
{
    __shared__ int map_s[128];

    const int b  = blockIdx.z;
    const int y  = blockIdx.y;
    const int x0 = blockIdx.x * 128;
    const int t  = threadIdx.x;

    const int pix_base = b * (NY * NX) + y * NX + x0;
    if (t < 128) {
        const int pix = pix_base + t;
        int v = g_map[pix];
        // self-validation: stale / zero-init entries point to a voxel whose
        // current pixel differs -> invalid.
        if (g_pix[v] != pix) v = -1;
        map_s[t] = v;
    }
    __syncthreads();

    const int xq  = (t & 31) * 4;
    const int row = t >> 5;                 // 0..7

    const int v0 = map_s[xq + 0];
    const int v1 = map_s[xq + 1];
    const int v2 = map_s[xq + 2];
    const int v3 = map_s[xq + 3];
    const bool any = (v0 >= 0) | (v1 >= 0) | (v2 >= 0) | (v3 >= 0);

    const size_t out_xbase = (size_t)y * NX + x0 + xq;

    #pragma unroll
    for (int k = 0; k < 8; k++) {
        const int c = row + k * 8;
        float4 val = make_float4(0.f, 0.f, 0.f, 0.f);
        if (any) {
            if (v0 >= 0) val.x = g_feats[(size_t)v0 * C_OUT + c];
            if (v1 >= 0) val.y = g_feats[(size_t)v1 * C_OUT + c];
            if (v2 >= 0) val.z = g_feats[(size_t)v2 * C_OUT + c];
            if (v3 >= 0) val.w = g_feats[(size_t)v3 * C_OUT + c];
        }
        float4* dst = reinterpret_cast<float4*>(
            out + ((size_t)(b * C_OUT + c)) * PLANE + out_xbase);
        __stcs(dst, val);   // streaming store: keep feats/map resident in L2
    }

    if (t < 32) {
        float4 occ = make_float4(v0 >= 0 ? 1.f : 0.f,
                                 v1 >= 0 ? 1.f : 0.f,
                                 v2 >= 0 ? 1.f : 0.f,
                                 v3 >= 0 ? 1.f : 0.f);
        float4* dst = reinterpret_cast<float4*>(
            out + CANVAS + (size_t)b * PLANE + out_xbase);
        __stcs(dst, occ);
    }
}

extern "C" void kernel_launch(void* const* d_in, const int* in_sizes, int n_in,
                              void* d_out, int out_size)
{
    const float* voxels     = (const float*)d_in[0];
    const int*   num_points = (const int*)  d_in[1];
    const int*   coors      = (const int*)  d_in[2];
    const float* W          = (const float*)d_in[3];
    const float* gamma      = (const float*)d_in[4];
    const float* beta       = (const float*)d_in[5];
    const float* rmean      = (const float*)d_in[6];
    const float* rvar       = (const float*)d_in[7];
    float* out = (float*)d_out;

    compute_feats_kernel<<<(V_NUM + 3) / 4, 128>>>(voxels, num_points, coors,
                                                   W, gamma, beta, rmean, rvar);

    dim3 grid(NX / 128, NY, B_NUM);
    render_kernel<<<grid, 256>>>(out);
}

// round 4
// speedup vs baseline: 2.4583x; 1.0037x over previous
#include <cuda_runtime.h>
#include <cstdint>

#define V_NUM 80000
#define P_NUM 20
#define C_OUT 64
#define NY 640
#define NX 640
#define B_NUM 4

static constexpr float BN_EPS = 0.001f;
static constexpr size_t PLANE  = (size_t)NY * NX;                 // 409600
static constexpr size_t CANVAS = (size_t)B_NUM * C_OUT * PLANE;   // 104857600
static constexpr int    MAP_N  = B_NUM * NY * NX;                 // 1638400

__device__ __constant__ float kVX   = 100.0f / 640.0f;
__device__ __constant__ float kXOFF = 100.0f / 640.0f * 0.5f - 50.0f;

// Scratch. g_map / g_pix are zero-initialized at module load; the
// self-validation scheme (g_pix[g_map[pix]] == pix) makes per-call clearing
// unnecessary.
__device__ float  g_feats[(size_t)V_NUM * C_OUT];   // 20.5 MB
__device__ int    g_map[MAP_N];                     // pixel -> voxel id
__device__ int    g_pix[V_NUM];                     // voxel id -> pixel
// Folded per-channel constants, paired (c, c+32):
// rows: 0:A 1:B 2:C 3:D 4:bb 5..9: sw4..sw8
__device__ float2 g_fold[10 * 32];

// ---------------------------------------------------------------------------
// Kernel 0: fold BN + weight sums once (1 warp).
// ---------------------------------------------------------------------------
__global__ void fold_kernel(const float* __restrict__ W,
                            const float* __restrict__ gamma,
                            const float* __restrict__ beta,
                            const float* __restrict__ rmean,
                            const float* __restrict__ rvar)
{
    const int t = threadIdx.x;           // 0..31
    if (t >= 32) return;
    const int c0 = t, c1 = t + 32;

    const float s0 = rsqrtf(rvar[c0] + BN_EPS) * gamma[c0];
    const float s1 = rsqrtf(rvar[c1] + BN_EPS) * gamma[c1];
    const float bb0 = beta[c0] - rmean[c0] * s0;
    const float bb1 = beta[c1] - rmean[c1] * s1;

    float sw0[9], sw1[9];
    #pragma unroll
    for (int i = 0; i < 9; i++) {
        sw0[i] = W[i * C_OUT + c0] * s0;
        sw1[i] = W[i * C_OUT + c1] * s1;
    }
    g_fold[0 * 32 + t] = make_float2(sw0[0] + sw0[4] + sw0[7],
                                     sw1[0] + sw1[4] + sw1[7]);   // A
    g_fold[1 * 32 + t] = make_float2(sw0[1] + sw0[5] + sw0[8],
                                     sw1[1] + sw1[5] + sw1[8]);   // B
    g_fold[2 * 32 + t] = make_float2(sw0[2] + sw0[6],
                                     sw1[2] + sw1[6]);            // C
    g_fold[3 * 32 + t] = make_float2(sw0[3], sw1[3]);             // D
    g_fold[4 * 32 + t] = make_float2(bb0, bb1);                   // bb
    #pragma unroll
    for (int i = 0; i < 5; i++)
        g_fold[(5 + i) * 32 + t] = make_float2(sw0[4 + i], sw1[4 + i]);
}

// ---------------------------------------------------------------------------
// Kernel 1: per-voxel features -> g_feats (coalesced), id <-> pixel links.
// One warp per voxel; lane handles channels {lane, lane+32}.
// h = x*A + y*B + z*C + w*D + E_v   (BN folded; E_v per-voxel constant)
// ---------------------------------------------------------------------------
__global__ void __launch_bounds__(128)
compute_feats_kernel(const float* __restrict__ voxels,
                     const int*   __restrict__ num_points,
                     const int*   __restrict__ coors)
{
    const int v = blockIdx.x * (blockDim.x >> 5) + (threadIdx.x >> 5);
    if (v >= V_NUM) return;
    const int lane = threadIdx.x & 31;

    const float4* __restrict__ vox =
        reinterpret_cast<const float4*>(voxels) + (size_t)v * P_NUM;

    int npv = num_points[v];
    npv = npv < 0 ? 0 : (npv > P_NUM ? P_NUM : npv);

    // folded channel constants (coalesced LDG.64)
    const float2 A  = g_fold[0 * 32 + lane];
    const float2 B  = g_fold[1 * 32 + lane];
    const float2 C  = g_fold[2 * 32 + lane];
    const float2 D  = g_fold[3 * 32 + lane];
    const float2 bb = g_fold[4 * 32 + lane];
    const float2 s4 = g_fold[5 * 32 + lane];
    const float2 s5 = g_fold[6 * 32 + lane];
    const float2 s6 = g_fold[7 * 32 + lane];
    const float2 s7 = g_fold[8 * 32 + lane];
    const float2 s8 = g_fold[9 * 32 + lane];

    // mean over valid points via warp reduction
    float sx = 0.f, sy = 0.f, sz = 0.f;
    if (lane < npv) {
        float4 pt = vox[lane];
        sx = pt.x; sy = pt.y; sz = pt.z;
    }
    #pragma unroll
    for (int o = 16; o; o >>= 1) {
        sx += __shfl_xor_sync(0xffffffffu, sx, o);
        sy += __shfl_xor_sync(0xffffffffu, sy, o);
        sz += __shfl_xor_sync(0xffffffffu, sz, o);
    }
    const float inv_n = 1.0f / (float)(npv > 1 ? npv : 1);
    const float mx = sx * inv_n, my = sy * inv_n, mz = sz * inv_n;

    const int b  = coors[v * 4 + 0];
    const int yy = coors[v * 4 + 2];
    const int xx = coors[v * 4 + 3];
    const float cx = (float)xx * kVX + kXOFF;
    const float cy = (float)yy * kVX + kXOFF;

    // per-voxel constant term
    const float E0 = bb.x - (mx * s4.x + my * s5.x + mz * s6.x
                           + cx * s7.x + cy * s8.x);
    const float E1 = bb.y - (mx * s4.y + my * s5.y + mz * s6.y
                           + cx * s7.y + cy * s8.y);

    // masked (zero-feature) points contribute relu(BN bias) to the max
    float m0 = (npv < P_NUM) ? fmaxf(bb.x, 0.0f) : -3.4e38f;
    float m1 = (npv < P_NUM) ? fmaxf(bb.y, 0.0f) : -3.4e38f;

    for (int p = 0; p < npv; p++) {
        const float4 pt = vox[p];
        float h0 = fmaf(pt.x, A.x, E0);
        float h1 = fmaf(pt.x, A.y, E1);
        h0 = fmaf(pt.y, B.x, h0);   h1 = fmaf(pt.y, B.y, h1);
        h0 = fmaf(pt.z, C.x, h0);   h1 = fmaf(pt.z, C.y, h1);
        h0 = fmaf(pt.w, D.x, h0);   h1 = fmaf(pt.w, D.y, h1);
        m0 = fmaxf(m0, fmaxf(h0, 0.0f));
        m1 = fmaxf(m1, fmaxf(h1, 0.0f));
    }

    g_feats[(size_t)v * C_OUT + lane]      = m0;
    g_feats[(size_t)v * C_OUT + lane + 32] = m1;
    if (lane == 0) {
        const int pix = b * (NY * NX) + yy * NX + xx;
        g_map[pix] = v;
        g_pix[v]   = pix;
    }
}

// ---------------------------------------------------------------------------
// Kernel 2: coalesced render of canvas + occ.
// Block = 256 threads, owns 128 pixels of one (b,y) row, all 64 channels.
// ---------------------------------------------------------------------------
__global__ void __launch_bounds__(256)
render_kernel(float* __restrict__ out)
{
    __shared__ int map_s[128];

    const int b  = blockIdx.z;
    const int y  = blockIdx.y;
    const int x0 = blockIdx.x * 128;
    const int t  = threadIdx.x;

    const int pix_base = b * (NY * NX) + y * NX + x0;
    if (t < 128) {
        const int pix = pix_base + t;
        int v = g_map[pix];
        if (g_pix[v] != pix) v = -1;   // stale / zero-init -> invalid
        map_s[t] = v;
    }
    __syncthreads();

    const int xq  = (t & 31) * 4;
    const int row = t >> 5;            // 0..7

    const int v0 = map_s[xq + 0];
    const int v1 = map_s[xq + 1];
    const int v2 = map_s[xq + 2];
    const int v3 = map_s[xq + 3];

    const size_t out_xbase = (size_t)y * NX + x0 + xq;

    #pragma unroll
    for (int k = 0; k < 8; k++) {
        const int c = row + k * 8;
        float4 val = make_float4(0.f, 0.f, 0.f, 0.f);
        if (v0 >= 0) val.x = g_feats[(size_t)v0 * C_OUT + c];
        if (v1 >= 0) val.y = g_feats[(size_t)v1 * C_OUT + c];
        if (v2 >= 0) val.z = g_feats[(size_t)v2 * C_OUT + c];
        if (v3 >= 0) val.w = g_feats[(size_t)v3 * C_OUT + c];
        float4* dst = reinterpret_cast<float4*>(
            out + ((size_t)(b * C_OUT + c)) * PLANE + out_xbase);
        __stcs(dst, val);              // streaming: keep feats/map in L2
    }

    if (t < 32) {
        float4 occ = make_float4(v0 >= 0 ? 1.f : 0.f,
                                 v1 >= 0 ? 1.f : 0.f,
                                 v2 >= 0 ? 1.f : 0.f,
                                 v3 >= 0 ? 1.f : 0.f);
        float4* dst = reinterpret_cast<float4*>(
            out + CANVAS + (size_t)b * PLANE + out_xbase);
        __stcs(dst, occ);
    }
}

extern "C" void kernel_launch(void* const* d_in, const int* in_sizes, int n_in,
                              void* d_out, int out_size)
{
    const float* voxels     = (const float*)d_in[0];
    const int*   num_points = (const int*)  d_in[1];
    const int*   coors      = (const int*)  d_in[2];
    const float* W          = (const float*)d_in[3];
    const float* gamma      = (const float*)d_in[4];
    const float* beta       = (const float*)d_in[5];
    const float* rmean      = (const float*)d_in[6];
    const float* rvar       = (const float*)d_in[7];
    float* out = (float*)d_out;

    fold_kernel<<<1, 32>>>(W, gamma, beta, rmean, rvar);

    compute_feats_kernel<<<(V_NUM + 3) / 4, 128>>>(voxels, num_points, coors);

    dim3 grid(NX / 128, NY, B_NUM);
    render_kernel<<<grid, 256>>>(out);
}